// round 16
// baseline (speedup 1.0000x reference)
#include <cuda_runtime.h>
#include <cstdint>

typedef unsigned long long u64;
typedef ulonglong2 u64x2;

// ---- packed f32x2 helpers --------------------------------------------------
__device__ __forceinline__ u64 pk2(float a, float b) {
    u64 r; asm("mov.b64 %0, {%1,%2};" : "=l"(r) : "f"(a), "f"(b)); return r;
}
__device__ __forceinline__ void up2(u64 v, float& a, float& b) {
    asm("mov.b64 {%0,%1}, %2;" : "=f"(a), "=f"(b) : "l"(v));
}
__device__ __forceinline__ u64 fma2(u64 a, u64 b, u64 c) {
    u64 d; asm("fma.rn.f32x2 %0, %1, %2, %3;" : "=l"(d) : "l"(a), "l"(b), "l"(c)); return d;
}
__device__ __forceinline__ u64 add2(u64 a, u64 b) {
    u64 d; asm("add.rn.f32x2 %0, %1, %2;" : "=l"(d) : "l"(a), "l"(b)); return d;
}

// ---- problem constants -----------------------------------------------------
constexpr int D      = 64;
constexpr int M      = 2048;
constexpr int K      = 8;
constexpr int NTOK   = 32768;       // B*S
constexpr int PAIRS  = 56;          // token pairs per CTA (tok p, tok p+56)
constexpr int TPC    = 112;         // tokens per CTA (296*112 = 33152 >= 32768)
constexpr int CT     = 128;         // codes per staged tile
constexpr int NTILES = M / CT;      // 16
constexpr int NT     = 128;         // threads per CTA (4 warps)
constexpr int NCTA   = 296;         // = 148 SMs x 2 CTAs: PERFECT single wave

// ---- dynamic smem layout (bytes) -------------------------------------------
constexpr int OFF_RP  = 0;                        // u64 RP[D][PAIRS]     28672
constexpr int OFF_CP  = OFF_RP + D * PAIRS * 8;   // u64 CP[D][CT] dup    65536
constexpr int OFF_C2  = OFF_CP + D * CT * 8;      // float C2[CT]           512
constexpr int OFF_R2  = OFF_C2 + CT * 4;          // u64 R2s[PAIRS]         512
constexpr int OFF_CHO = OFF_R2 + 512;             // int2 CHO[PAIRS]        512
constexpr int SMEMB   = OFF_CHO + 512;            // 95744 -> 2 CTAs/SM
constexpr int OFF_MN  = OFF_CP;                   // float4 MN[NT][7] aliases CP

// 128 threads; thread (a = t&7, cg = t>>3) owns pairs {7a..7a+6} x codes
// {8cg..8cg+7} -> 56 FMA2 accumulators (7x8 block). CP stores PRE-DUPLICATED
// {c,c} u64 -> inner loop has ZERO duplication MOVs on the fma pipe; cc read
// directly via 4x LDS.128. Grid 296 = 148x2 -> perfectly balanced single
// wave; staging/barriers/L2-traffic per token HALVED vs R15 (codebook
// amortized over 112 tokens). Token ids clamped to NTOK-1 (duplicates
// recompute bit-identically; benign). Numerics bit-identical to all passing
// rounds (rel_err 0.0 x12): ascending-d FMA chains for cross/r2;
// d2 = (r2 - 2*cross) + c2 with c2 = two ascending 32-dim half-chains
// summed; strict-< ascending per-thread argmin + lexicographic (d2, idx)
// cross-thread merge over ascending code blocks.
__global__ void __launch_bounds__(NT, 2)
rvq_kernel(const float* __restrict__ x, const float* __restrict__ cb,
           float* __restrict__ qout, float* __restrict__ idxout)
{
    extern __shared__ __align__(16) char sm[];
    u64*    RP  = (u64*)(sm + OFF_RP);
    u64*    CP  = (u64*)(sm + OFF_CP);
    float*  C2  = (float*)(sm + OFF_C2);
    u64*    R2s = (u64*)(sm + OFF_R2);
    int2*   CHO = (int2*)(sm + OFF_CHO);
    float4* MN  = (float4*)(sm + OFF_MN);

    const int t    = threadIdx.x;
    const int base = blockIdx.x * TPC;
    const int pq   = t >> 1;        // pair for init/update/output (0..63; <56 active)
    const int qh   = t & 1;         // dim half (0..1): 32 dims each
    const bool pact = (pq < PAIRS);
    const int tok0 = pact ? min(base + pq, NTOK - 1) : 0;
    const int tok1 = pact ? min(base + PAIRS + pq, NTOK - 1) : 0;
    const int a    = t & 7;         // pair stripe: pairs 7a..7a+6
    const int cg   = t >> 3;        // code group (0..15), 8 codes each

    const u64 NEG1 = pk2(-1.0f, -1.0f);
    const u64 NEG2 = pk2(-2.0f, -2.0f);
    const float FMAX = 3.402823466e38f;

    // ---- init: pack x into RP (pair p = tokens p, p+56 clamped) ----
    if (pact) {
        const float4* xa = (const float4*)(x + (size_t)tok0 * D) + qh * 8;
        const float4* xb = (const float4*)(x + (size_t)tok1 * D) + qh * 8;
        #pragma unroll
        for (int i = 0; i < 8; i++) {
            float4 va = xa[i], vb = xb[i];
            int d = qh * 32 + i * 4;
            RP[(d+0)*PAIRS + pq] = pk2(va.x, vb.x);
            RP[(d+1)*PAIRS + pq] = pk2(va.y, vb.y);
            RP[(d+2)*PAIRS + pq] = pk2(va.z, vb.z);
            RP[(d+3)*PAIRS + pq] = pk2(va.w, vb.w);
        }
    }
    __syncthreads();

    for (int k = 0; k < K; k++) {
        const float* cbk = cb + (size_t)k * M * D;

        // ---- r2 per pair: ascending-d packed FMA chain ----
        if (t < PAIRS) {
            u64 n2 = 0ull;
            #pragma unroll 8
            for (int d = 0; d < D; d++) { u64 v = RP[d*PAIRS + t]; n2 = fma2(v, v, n2); }
            R2s[t] = n2;
        }
        __syncthreads();   // R2s visible before r2v reads

        u64 r2v[7];
        #pragma unroll
        for (int j = 0; j < 7; j++) r2v[j] = R2s[7*a + j];

        float mlo[7], mhi[7]; int ilo[7], ihi[7];
        #pragma unroll
        for (int s = 0; s < 7; s++) {
            mlo[s] = FMAX; mhi[s] = FMAX; ilo[s] = 0; ihi[s] = 0;
        }

        for (int tile = 0; tile < NTILES; tile++) {
            // ---- stage 128 codes (code t per thread), PRE-DUPLICATED u64 ----
            {
                const int c0 = tile * CT + t;
                const float4* s0 = (const float4*)(cbk + (size_t)c0 * D);
                float c2a = 0.0f, c2b = 0.0f;
                #pragma unroll
                for (int i = 0; i < 8; i++) {          // dims 0..31
                    float4 v = s0[i]; int d = 4*i;
                    CP[(d+0)*CT + t] = pk2(v.x, v.x);
                    CP[(d+1)*CT + t] = pk2(v.y, v.y);
                    CP[(d+2)*CT + t] = pk2(v.z, v.z);
                    CP[(d+3)*CT + t] = pk2(v.w, v.w);
                    c2a = fmaf(v.x,v.x,c2a); c2a = fmaf(v.y,v.y,c2a);
                    c2a = fmaf(v.z,v.z,c2a); c2a = fmaf(v.w,v.w,c2a);
                }
                #pragma unroll
                for (int i = 8; i < 16; i++) {         // dims 32..63
                    float4 v = s0[i]; int d = 4*i;
                    CP[(d+0)*CT + t] = pk2(v.x, v.x);
                    CP[(d+1)*CT + t] = pk2(v.y, v.y);
                    CP[(d+2)*CT + t] = pk2(v.z, v.z);
                    CP[(d+3)*CT + t] = pk2(v.w, v.w);
                    c2b = fmaf(v.x,v.x,c2b); c2b = fmaf(v.y,v.y,c2b);
                    c2b = fmaf(v.z,v.z,c2b); c2b = fmaf(v.w,v.w,c2b);
                }
                C2[t] = c2a + c2b;   // two-half c2 sum
            }
            __syncthreads();

            // ---- cross: 7 pairs x 8 codes per thread, ascending-d chains ----
            u64 acc[7][8];
            #pragma unroll
            for (int p = 0; p < 7; p++)
                #pragma unroll
                for (int c = 0; c < 8; c++) acc[p][c] = 0ull;

            #pragma unroll 2
            for (int d = 0; d < D; d++) {
                const u64* rp = RP + d * PAIRS + 7*a;
                u64 rr[7];
                #pragma unroll
                for (int j = 0; j < 7; j++) rr[j] = rp[j];
                const u64x2* cf = (const u64x2*)(CP + d*CT + 8*cg);
                u64x2 cA = cf[0], cB = cf[1], cC = cf[2], cD = cf[3];
                #pragma unroll
                for (int p = 0; p < 7; p++) {
                    acc[p][0] = fma2(rr[p], cA.x, acc[p][0]);
                    acc[p][1] = fma2(rr[p], cA.y, acc[p][1]);
                    acc[p][2] = fma2(rr[p], cB.x, acc[p][2]);
                    acc[p][3] = fma2(rr[p], cB.y, acc[p][3]);
                    acc[p][4] = fma2(rr[p], cC.x, acc[p][4]);
                    acc[p][5] = fma2(rr[p], cC.y, acc[p][5]);
                    acc[p][6] = fma2(rr[p], cD.x, acc[p][6]);
                    acc[p][7] = fma2(rr[p], cD.y, acc[p][7]);
                }
            }

            // ---- d2 + running argmin (ascending code order per pair) ----
            const int jb = tile * CT + cg * 8;
            float4 c2q0 = *(const float4*)(C2 + cg*8);
            float4 c2q1 = *(const float4*)(C2 + cg*8 + 4);
            u64 cd[8];
            cd[0] = pk2(c2q0.x, c2q0.x); cd[1] = pk2(c2q0.y, c2q0.y);
            cd[2] = pk2(c2q0.z, c2q0.z); cd[3] = pk2(c2q0.w, c2q0.w);
            cd[4] = pk2(c2q1.x, c2q1.x); cd[5] = pk2(c2q1.y, c2q1.y);
            cd[6] = pk2(c2q1.z, c2q1.z); cd[7] = pk2(c2q1.w, c2q1.w);
            #pragma unroll
            for (int c = 0; c < 8; c++) {
                #pragma unroll
                for (int p = 0; p < 7; p++) {
                    float lo, hi;
                    up2(add2(fma2(acc[p][c], NEG2, r2v[p]), cd[c]), lo, hi);
                    if (lo < mlo[p]) { mlo[p] = lo; ilo[p] = jb + c; }
                    if (hi < mhi[p]) { mhi[p] = hi; ihi[p] = jb + c; }
                }
            }
            __syncthreads();   // CP/C2 consumed; safe to restage / alias MN
        }

        // ---- cross-thread argmin merge (MN aliases CP) ----
        #pragma unroll
        for (int s = 0; s < 7; s++)
            MN[t*7 + s] = make_float4(mlo[s], __int_as_float(ilo[s]),
                                      mhi[s], __int_as_float(ihi[s]));
        __syncthreads();

        if (t < PAIRS) {
            const int p  = t;
            const int pa = p / 7;       // stripe of pair p (0..7)
            const int sl = p % 7;       // slot within stripe
            float g0 = FMAX, g1 = FMAX;
            int gi0 = 0, gi1 = 0;
            #pragma unroll
            for (int c = 0; c < 16; c++) {   // ascending cg = ascending code blocks
                float4 v = MN[(c*8 + pa)*7 + sl];
                float va = v.x, vb = v.z;
                int ia = __float_as_int(v.y), ib = __float_as_int(v.w);
                if (va < g0 || (va == g0 && ia < gi0)) { g0 = va; gi0 = ia; }
                if (vb < g1 || (vb == g1 && ib < gi1)) { g1 = vb; gi1 = ib; }
            }
            CHO[p] = make_int2(gi0, gi1);
            if (idxout) {
                // clamped ids: duplicated tokens write identical values
                idxout[(size_t)k * NTOK + min(base + p, NTOK - 1)]         = (float)gi0;
                idxout[(size_t)k * NTOK + min(base + PAIRS + p, NTOK - 1)] = (float)gi1;
            }
        }
        __syncthreads();

        // ---- residual update: RP[d][p] -= code (exact fma(-1,c,r)) ----
        if (pact) {
            int2 ch = CHO[pq];
            const float4* ca = (const float4*)(cbk + (size_t)ch.x * D) + qh * 8;
            const float4* cw = (const float4*)(cbk + (size_t)ch.y * D) + qh * 8;
            #pragma unroll
            for (int i = 0; i < 8; i++) {
                float4 u = ca[i], w = cw[i];
                int d = qh * 32 + i * 4;
                RP[(d+0)*PAIRS+pq] = fma2(pk2(u.x, w.x), NEG1, RP[(d+0)*PAIRS+pq]);
                RP[(d+1)*PAIRS+pq] = fma2(pk2(u.y, w.y), NEG1, RP[(d+1)*PAIRS+pq]);
                RP[(d+2)*PAIRS+pq] = fma2(pk2(u.z, w.z), NEG1, RP[(d+2)*PAIRS+pq]);
                RP[(d+3)*PAIRS+pq] = fma2(pk2(u.w, w.w), NEG1, RP[(d+3)*PAIRS+pq]);
            }
        }
        __syncthreads();
    }

    // ---- output: quantized = x - residual (exact elementwise) ----
    if (pact) {
        const float4* xa = (const float4*)(x + (size_t)tok0 * D) + qh * 8;
        const float4* xb = (const float4*)(x + (size_t)tok1 * D) + qh * 8;
        float4* qa = (float4*)(qout + (size_t)tok0 * D) + qh * 8;
        float4* qb = (float4*)(qout + (size_t)tok1 * D) + qh * 8;
        #pragma unroll
        for (int i = 0; i < 8; i++) {
            float4 va = xa[i], vb = xb[i];
            float4 oa, ob; float lo, hi;
            int d = qh * 32 + i * 4;
            up2(RP[(d+0)*PAIRS+pq], lo, hi); oa.x = va.x - lo; ob.x = vb.x - hi;
            up2(RP[(d+1)*PAIRS+pq], lo, hi); oa.y = va.y - lo; ob.y = vb.y - hi;
            up2(RP[(d+2)*PAIRS+pq], lo, hi); oa.z = va.z - lo; ob.z = vb.z - hi;
            up2(RP[(d+3)*PAIRS+pq], lo, hi); oa.w = va.w - lo; ob.w = vb.w - hi;
            qa[i] = oa; qb[i] = ob;
        }
    }
}

extern "C" void kernel_launch(void* const* d_in, const int* in_sizes, int n_in,
                              void* d_out, int out_size)
{
    const float* x  = (const float*)d_in[0];
    const float* cb = (const float*)d_in[1];
    if (n_in >= 2 && in_sizes[0] == K * M * D && in_sizes[1] == NTOK * D) {
        x  = (const float*)d_in[1];
        cb = (const float*)d_in[0];
    }
    float* q = (float*)d_out;
    float* idxf = (out_size >= NTOK * D + K * NTOK) ? (q + (size_t)NTOK * D) : nullptr;

    cudaFuncSetAttribute(rvq_kernel, cudaFuncAttributeMaxDynamicSharedMemorySize, SMEMB);
    rvq_kernel<<<NCTA, NT, SMEMB>>>(x, cb, q, idxf);
}

// round 17
// speedup vs baseline: 1.5419x; 1.5419x over previous
#include <cuda_runtime.h>
#include <cstdint>

typedef unsigned long long u64;
typedef ulonglong2 u64x2;

// ---- packed f32x2 helpers --------------------------------------------------
__device__ __forceinline__ u64 pk2(float a, float b) {
    u64 r; asm("mov.b64 %0, {%1,%2};" : "=l"(r) : "f"(a), "f"(b)); return r;
}
__device__ __forceinline__ void up2(u64 v, float& a, float& b) {
    asm("mov.b64 {%0,%1}, %2;" : "=f"(a), "=f"(b) : "l"(v));
}
__device__ __forceinline__ u64 fma2(u64 a, u64 b, u64 c) {
    u64 d; asm("fma.rn.f32x2 %0, %1, %2, %3;" : "=l"(d) : "l"(a), "l"(b), "l"(c)); return d;
}
__device__ __forceinline__ u64 add2(u64 a, u64 b) {
    u64 d; asm("add.rn.f32x2 %0, %1, %2;" : "=l"(d) : "l"(a), "l"(b)); return d;
}

// ---- problem constants -----------------------------------------------------
constexpr int D      = 64;
constexpr int M      = 2048;
constexpr int K      = 8;
constexpr int NTOK   = 32768;       // B*S
constexpr int PAIRS  = 28;          // token pairs per CTA (tok p, tok p+28)
constexpr int TPC    = 56;          // tokens per CTA (592*56 = 33152 >= 32768)
constexpr int CT     = 64;          // codes per tile (double-buffered)
constexpr int NTILES = M / CT;      // 32
constexpr int NT     = 64;          // threads per CTA (2 warps)
constexpr int NCTA   = 592;         // = 148 SMs x 4 CTAs: PERFECT single wave

// ---- dynamic smem layout (bytes) -------------------------------------------
constexpr int OFF_RP  = 0;                        // u64   RP[D][PAIRS]   14336
constexpr int OFF_CP  = OFF_RP + D * PAIRS * 8;   // float CP[2][D][CT]   32768
constexpr int OFF_C2  = OFF_CP + 2 * D * CT * 4;  // float C2[2][CT]        512
constexpr int OFF_R2  = OFF_C2 + 2 * CT * 4;      // u64   R2s[PAIRS]       256
constexpr int OFF_CHO = OFF_R2 + 256;             // int2  CHO[PAIRS]       256
constexpr int SMEMB   = OFF_CHO + 256;            // 48384 -> 4 CTAs/SM
constexpr int OFF_MN  = OFF_CP;                   // float4 MN[NT][7] aliases CP

// Champion geometry (R15) + double-buffered CP pipeline (R10 chunk pattern):
// 64 threads; thread (a = t&3, cg = t>>2) owns pairs {7a..7a+6} x codes
// {4cg..4cg+3} -> 28 FMA2 accumulators (7x4 block). Per tile: prefetch next
// tile's LDGs -> compute dims 0..31 -> STS chunk A -> prefetch B -> compute
// 32..63 -> STS B -> eval -> ONE barrier. LDG/STS hidden under compute.
// Token ids clamped to NTOK-1 (duplicates recompute bit-identically; benign).
// Numerics bit-identical to all passing rounds (rel_err 0.0 x13):
// ascending-d FMA chains for cross/r2; d2 = (r2 - 2*cross) + c2 with c2 =
// two ascending 32-dim half-chains summed; strict-< ascending per-thread
// argmin + lexicographic (d2, idx) cross-thread merge over ascending blocks.
__global__ void __launch_bounds__(NT, 4)
rvq_kernel(const float* __restrict__ x, const float* __restrict__ cb,
           float* __restrict__ qout, float* __restrict__ idxout)
{
    extern __shared__ __align__(16) char sm[];
    u64*    RP  = (u64*)(sm + OFF_RP);
    float*  CP  = (float*)(sm + OFF_CP);
    float*  C2  = (float*)(sm + OFF_C2);
    u64*    R2s = (u64*)(sm + OFF_R2);
    int2*   CHO = (int2*)(sm + OFF_CHO);
    float4* MN  = (float4*)(sm + OFF_MN);

    const int t    = threadIdx.x;
    const int base = blockIdx.x * TPC;
    const int pq   = t >> 1;        // pair for init/update/output (0..31; <28 active)
    const int qh   = t & 1;         // dim half (0..1): 32 dims each
    const bool pact = (pq < PAIRS);
    const int tok0 = pact ? min(base + pq, NTOK - 1) : 0;
    const int tok1 = pact ? min(base + PAIRS + pq, NTOK - 1) : 0;
    const int a    = t & 3;         // pair stripe: pairs 7a..7a+6
    const int cg   = t >> 2;        // code group (0..15), 4 codes each

    const u64 NEG1 = pk2(-1.0f, -1.0f);
    const u64 NEG2 = pk2(-2.0f, -2.0f);
    const float FMAX = 3.402823466e38f;

    // ---- init: pack x into RP (pair p = tokens p, p+28 clamped) ----
    if (pact) {
        const float4* xa = (const float4*)(x + (size_t)tok0 * D) + qh * 8;
        const float4* xb = (const float4*)(x + (size_t)tok1 * D) + qh * 8;
        #pragma unroll
        for (int i = 0; i < 8; i++) {
            float4 va = xa[i], vb = xb[i];
            int d = qh * 32 + i * 4;
            RP[(d+0)*PAIRS + pq] = pk2(va.x, vb.x);
            RP[(d+1)*PAIRS + pq] = pk2(va.y, vb.y);
            RP[(d+2)*PAIRS + pq] = pk2(va.z, vb.z);
            RP[(d+3)*PAIRS + pq] = pk2(va.w, vb.w);
        }
    }
    __syncthreads();

    for (int k = 0; k < K; k++) {
        const float* cbk = cb + (size_t)k * M * D;

        // ---- r2 per pair: ascending-d packed FMA chain ----
        if (t < PAIRS) {
            u64 n2 = 0ull;
            #pragma unroll 8
            for (int d = 0; d < D; d++) { u64 v = RP[d*PAIRS + t]; n2 = fma2(v, v, n2); }
            R2s[t] = n2;
        }
        __syncthreads();   // R2s visible before r2v reads

        u64 r2v[7];
        #pragma unroll
        for (int j = 0; j < 7; j++) r2v[j] = R2s[7*a + j];

        float mlo[7], mhi[7]; int ilo[7], ihi[7];
        #pragma unroll
        for (int s = 0; s < 7; s++) {
            mlo[s] = FMAX; mhi[s] = FMAX; ilo[s] = 0; ihi[s] = 0;
        }

        // ---- prologue: stage tile 0 into buffer 0 (code t) ----
        {
            const float4* s0 = (const float4*)(cbk + (size_t)t * D);
            float c2a = 0.0f, c2b = 0.0f;
            #pragma unroll
            for (int i = 0; i < 8; i++) {              // dims 0..31
                float4 v = s0[i]; int d = 4*i;
                CP[(d+0)*CT + t] = v.x; CP[(d+1)*CT + t] = v.y;
                CP[(d+2)*CT + t] = v.z; CP[(d+3)*CT + t] = v.w;
                c2a = fmaf(v.x,v.x,c2a); c2a = fmaf(v.y,v.y,c2a);
                c2a = fmaf(v.z,v.z,c2a); c2a = fmaf(v.w,v.w,c2a);
            }
            #pragma unroll
            for (int i = 8; i < 16; i++) {             // dims 32..63
                float4 v = s0[i]; int d = 4*i;
                CP[(d+0)*CT + t] = v.x; CP[(d+1)*CT + t] = v.y;
                CP[(d+2)*CT + t] = v.z; CP[(d+3)*CT + t] = v.w;
                c2b = fmaf(v.x,v.x,c2b); c2b = fmaf(v.y,v.y,c2b);
                c2b = fmaf(v.z,v.z,c2b); c2b = fmaf(v.w,v.w,c2b);
            }
            C2[t] = c2a + c2b;   // two-half c2 sum
        }
        __syncthreads();

        for (int tile = 0; tile < NTILES; tile++) {
            const int   buf  = tile & 1;
            const int   nbuf = buf ^ 1;
            const float* CPb = CP + buf  * (D * CT);
            float*       CPn = CP + nbuf * (D * CT);
            const bool  more = (tile + 1 < NTILES);
            const float* nsrc = cbk + (size_t)((tile + 1) * CT + t) * D;

            u64 acc[7][4];
            #pragma unroll
            for (int p = 0; p < 7; p++)
                #pragma unroll
                for (int c = 0; c < 4; c++) acc[p][c] = 0ull;

            // ---- prefetch chunk A of tile+1 (dims 0..31) ----
            float4 la[8];
            if (more) {
                #pragma unroll
                for (int i = 0; i < 8; i++) la[i] = *(const float4*)(nsrc + 4*i);
            }

            // ---- compute dims 0..31 on CP[buf] ----
            #pragma unroll 4
            for (int d = 0; d < 32; d++) {
                const u64* rp = RP + d * PAIRS + 7*a;
                u64 rr[7];
                #pragma unroll
                for (int j = 0; j < 7; j++) rr[j] = rp[j];
                float4 cf = *(const float4*)(CPb + d*CT + cg*4);
                u64 cc0 = pk2(cf.x, cf.x), cc1 = pk2(cf.y, cf.y);
                u64 cc2 = pk2(cf.z, cf.z), cc3 = pk2(cf.w, cf.w);
                #pragma unroll
                for (int p = 0; p < 7; p++) {
                    acc[p][0] = fma2(rr[p], cc0, acc[p][0]);
                    acc[p][1] = fma2(rr[p], cc1, acc[p][1]);
                    acc[p][2] = fma2(rr[p], cc2, acc[p][2]);
                    acc[p][3] = fma2(rr[p], cc3, acc[p][3]);
                }
            }

            // ---- drain chunk A: c2 half + STS into CP[nbuf] ----
            float c2h = 0.f;
            if (more) {
                #pragma unroll
                for (int i = 0; i < 8; i++) {
                    float4 v = la[i]; int d = 4*i;
                    CPn[(d+0)*CT + t] = v.x; CPn[(d+1)*CT + t] = v.y;
                    CPn[(d+2)*CT + t] = v.z; CPn[(d+3)*CT + t] = v.w;
                    c2h = fmaf(v.x,v.x,c2h); c2h = fmaf(v.y,v.y,c2h);
                    c2h = fmaf(v.z,v.z,c2h); c2h = fmaf(v.w,v.w,c2h);
                }
            }

            // ---- prefetch chunk B of tile+1 (dims 32..63) ----
            float4 lb[8];
            if (more) {
                #pragma unroll
                for (int i = 0; i < 8; i++) lb[i] = *(const float4*)(nsrc + 32 + 4*i);
            }

            // ---- compute dims 32..63 on CP[buf] ----
            #pragma unroll 4
            for (int d = 32; d < 64; d++) {
                const u64* rp = RP + d * PAIRS + 7*a;
                u64 rr[7];
                #pragma unroll
                for (int j = 0; j < 7; j++) rr[j] = rp[j];
                float4 cf = *(const float4*)(CPb + d*CT + cg*4);
                u64 cc0 = pk2(cf.x, cf.x), cc1 = pk2(cf.y, cf.y);
                u64 cc2 = pk2(cf.z, cf.z), cc3 = pk2(cf.w, cf.w);
                #pragma unroll
                for (int p = 0; p < 7; p++) {
                    acc[p][0] = fma2(rr[p], cc0, acc[p][0]);
                    acc[p][1] = fma2(rr[p], cc1, acc[p][1]);
                    acc[p][2] = fma2(rr[p], cc2, acc[p][2]);
                    acc[p][3] = fma2(rr[p], cc3, acc[p][3]);
                }
            }

            // ---- drain chunk B: c2 half + STS; publish C2[nbuf] ----
            if (more) {
                float c2r = 0.f;
                #pragma unroll
                for (int i = 0; i < 8; i++) {
                    float4 v = lb[i]; int d = 32 + 4*i;
                    CPn[(d+0)*CT + t] = v.x; CPn[(d+1)*CT + t] = v.y;
                    CPn[(d+2)*CT + t] = v.z; CPn[(d+3)*CT + t] = v.w;
                    c2r = fmaf(v.x,v.x,c2r); c2r = fmaf(v.y,v.y,c2r);
                    c2r = fmaf(v.z,v.z,c2r); c2r = fmaf(v.w,v.w,c2r);
                }
                C2[nbuf*CT + t] = c2h + c2r;   // two-half c2 sum
            }

            // ---- d2 + running argmin (ascending code order per pair) ----
            const int jb = tile * CT + cg * 4;
            float4 c2q = *(const float4*)(C2 + buf*CT + cg*4);
            u64 cd0 = pk2(c2q.x, c2q.x), cd1 = pk2(c2q.y, c2q.y);
            u64 cd2 = pk2(c2q.z, c2q.z), cd3 = pk2(c2q.w, c2q.w);
            u64 cd[4] = {cd0, cd1, cd2, cd3};
            #pragma unroll
            for (int c = 0; c < 4; c++) {
                #pragma unroll
                for (int p = 0; p < 7; p++) {
                    float lo, hi;
                    up2(add2(fma2(acc[p][c], NEG2, r2v[p]), cd[c]), lo, hi);
                    if (lo < mlo[p]) { mlo[p] = lo; ilo[p] = jb + c; }
                    if (hi < mhi[p]) { mhi[p] = hi; ihi[p] = jb + c; }
                }
            }
            __syncthreads();   // nbuf staged; buf consumed -> swap
        }

        // ---- cross-thread argmin merge (MN aliases CP) ----
        #pragma unroll
        for (int s = 0; s < 7; s++)
            MN[t*7 + s] = make_float4(mlo[s], __int_as_float(ilo[s]),
                                      mhi[s], __int_as_float(ihi[s]));
        __syncthreads();

        if (t < PAIRS) {
            const int p  = t;
            const int pa = p / 7;       // stripe of pair p (0..3)
            const int sl = p % 7;       // slot within stripe
            float g0 = FMAX, g1 = FMAX;
            int gi0 = 0, gi1 = 0;
            #pragma unroll
            for (int c = 0; c < 16; c++) {   // ascending cg = ascending code blocks
                float4 v = MN[(c*4 + pa)*7 + sl];
                float va = v.x, vb = v.z;
                int ia = __float_as_int(v.y), ib = __float_as_int(v.w);
                if (va < g0 || (va == g0 && ia < gi0)) { g0 = va; gi0 = ia; }
                if (vb < g1 || (vb == g1 && ib < gi1)) { g1 = vb; gi1 = ib; }
            }
            CHO[p] = make_int2(gi0, gi1);
            if (idxout) {
                // clamped ids: duplicated tokens write identical values
                idxout[(size_t)k * NTOK + min(base + p, NTOK - 1)]         = (float)gi0;
                idxout[(size_t)k * NTOK + min(base + PAIRS + p, NTOK - 1)] = (float)gi1;
            }
        }
        __syncthreads();

        // ---- residual update: RP[d][p] -= code (exact fma(-1,c,r)) ----
        if (pact) {
            int2 ch = CHO[pq];
            const float4* ca = (const float4*)(cbk + (size_t)ch.x * D) + qh * 8;
            const float4* cw = (const float4*)(cbk + (size_t)ch.y * D) + qh * 8;
            #pragma unroll
            for (int i = 0; i < 8; i++) {
                float4 u = ca[i], w = cw[i];
                int d = qh * 32 + i * 4;
                RP[(d+0)*PAIRS+pq] = fma2(pk2(u.x, w.x), NEG1, RP[(d+0)*PAIRS+pq]);
                RP[(d+1)*PAIRS+pq] = fma2(pk2(u.y, w.y), NEG1, RP[(d+1)*PAIRS+pq]);
                RP[(d+2)*PAIRS+pq] = fma2(pk2(u.z, w.z), NEG1, RP[(d+2)*PAIRS+pq]);
                RP[(d+3)*PAIRS+pq] = fma2(pk2(u.w, w.w), NEG1, RP[(d+3)*PAIRS+pq]);
            }
        }
        __syncthreads();
    }

    // ---- output: quantized = x - residual (exact elementwise) ----
    if (pact) {
        const float4* xa = (const float4*)(x + (size_t)tok0 * D) + qh * 8;
        const float4* xb = (const float4*)(x + (size_t)tok1 * D) + qh * 8;
        float4* qa = (float4*)(qout + (size_t)tok0 * D) + qh * 8;
        float4* qb = (float4*)(qout + (size_t)tok1 * D) + qh * 8;
        #pragma unroll
        for (int i = 0; i < 8; i++) {
            float4 va = xa[i], vb = xb[i];
            float4 oa, ob; float lo, hi;
            int d = qh * 32 + i * 4;
            up2(RP[(d+0)*PAIRS+pq], lo, hi); oa.x = va.x - lo; ob.x = vb.x - hi;
            up2(RP[(d+1)*PAIRS+pq], lo, hi); oa.y = va.y - lo; ob.y = vb.y - hi;
            up2(RP[(d+2)*PAIRS+pq], lo, hi); oa.z = va.z - lo; ob.z = vb.z - hi;
            up2(RP[(d+3)*PAIRS+pq], lo, hi); oa.w = va.w - lo; ob.w = vb.w - hi;
            qa[i] = oa; qb[i] = ob;
        }
    }
}

extern "C" void kernel_launch(void* const* d_in, const int* in_sizes, int n_in,
                              void* d_out, int out_size)
{
    const float* x  = (const float*)d_in[0];
    const float* cb = (const float*)d_in[1];
    if (n_in >= 2 && in_sizes[0] == K * M * D && in_sizes[1] == NTOK * D) {
        x  = (const float*)d_in[1];
        cb = (const float*)d_in[0];
    }
    float* q = (float*)d_out;
    float* idxf = (out_size >= NTOK * D + K * NTOK) ? (q + (size_t)NTOK * D) : nullptr;

    cudaFuncSetAttribute(rvq_kernel, cudaFuncAttributeMaxDynamicSharedMemorySize, SMEMB);
    rvq_kernel<<<NCTA, NT, SMEMB>>>(x, cb, q, idxf);
}